// round 14
// baseline (speedup 1.0000x reference)
#include <cuda_runtime.h>
#include <cstdint>

// Problem constants
#define PB 8
#define PN 8192
#define PM 2048
#define PC 64
#define PS 32
#define OUTC 67              // 3 + 64
#define R2 1.0f

// Scratch (allocation-free rule: __device__ globals)
__device__ int    g_idx[PB * PM * PS];          // 2 MB
__device__ float  g_featT[PB * PN * PC];        // 16 MB, [b][n][c]
__device__ float4 g_xyz4[PB * PN];              // 1 MB, (x,y,z,p2)

// ---------------------------------------------------------------------------
// Kernel 0: pack xyz -> float4 with precomputed p2 (reference rounding)
// ---------------------------------------------------------------------------
__global__ __launch_bounds__(256) void pack_kernel(const float* __restrict__ xyz)
{
    const int i = blockIdx.x * blockDim.x + threadIdx.x;   // 0 .. B*N-1
    if (i >= PB * PN) return;
    const float x = xyz[i * 3 + 0];
    const float y = xyz[i * 3 + 1];
    const float z = xyz[i * 3 + 2];
    const float p2 = __fadd_rn(__fadd_rn(__fmul_rn(x, x), __fmul_rn(y, y)),
                               __fmul_rn(z, z));
    g_xyz4[i] = make_float4(x, y, z, p2);
}

// ---------------------------------------------------------------------------
// Kernel 1: transpose (DRAM-bound) + ball query (latency-bound) fused by
// blockIdx — independent inputs, complementary bottlenecks. (R8 version, 16us)
// blocks 0..1023   : transpose tiles (32c x 128n, float4 loads)
// blocks 1024..3071: ball query, 8 warps/block, 1 query/warp, 256 pts/iter
// ---------------------------------------------------------------------------
__global__ __launch_bounds__(256) void mid_kernel(
    const float* __restrict__ f, const float* __restrict__ new_xyz)
{
    __shared__ union {
        float4 tile[32][33];      // 16,896 B (transpose path)
        int    slots[8][PS];      //  1,024 B (query path)
    } sm;

    const int bid  = blockIdx.x;
    const int tx   = threadIdx.x & 31;
    const int ty   = threadIdx.x >> 5;     // 0..7

    if (bid < 1024) {
        // ---- transpose path ----
        const int b   = bid >> 7;                 // /128
        const int rem = bid & 127;
        const int c0  = (rem >> 6) << 5;          // 0 or 32
        const int n0  = (rem & 63) << 7;          // 0..8064 step 128

#pragma unroll
        for (int k = 0; k < 4; ++k) {
            const int c = ty + (k << 3);          // 0..31
            const float4* src =
                (const float4*)(f + ((size_t)b * PC + c0 + c) * PN + n0);
            sm.tile[c][tx] = src[tx];
        }
        __syncthreads();

        const float* tf = (const float*)&sm.tile[tx][0];  // 132 floats (c=tx)
#pragma unroll
        for (int i = 0; i < 16; ++i) {
            const int n = (i << 3) + ty;          // 0..127
            g_featT[((size_t)b * PN + n0 + n) * PC + c0 + tx] = tf[n];
        }
    } else {
        // ---- ball query path ----
        const int wid  = (bid - 1024) * 8 + ty;   // global query 0..16383
        const int lane = tx;
        const int b = wid >> 11;
        const int m = wid & (PM - 1);

        const float* q = new_xyz + ((size_t)b * PM + m) * 3;
        const float qx = q[0], qy = q[1], qz = q[2];
        const float q2 = __fadd_rn(__fadd_rn(__fmul_rn(qx, qx), __fmul_rn(qy, qy)),
                                   __fmul_rn(qz, qz));

        int* slot = sm.slots[ty];
        const float4* base4 = g_xyz4 + (size_t)b * PN;
        int cnt = 0;
        for (int n0 = 0; n0 < PN && cnt < PS; n0 += 256) {
            float4 cs[8];
#pragma unroll
            for (int k = 0; k < 8; ++k)
                cs[k] = base4[n0 + (k << 5) + lane];
#pragma unroll
            for (int k = 0; k < 8; ++k) {
                const float4 p = cs[k];
                const float qd = __fadd_rn(__fadd_rn(__fmul_rn(qx, p.x), __fmul_rn(qy, p.y)),
                                           __fmul_rn(qz, p.z));
                const float d2 = __fadd_rn(__fadd_rn(q2, p.w), -__fmul_rn(2.0f, qd));
                const bool valid = d2 < R2;
                const unsigned bal = __ballot_sync(0xffffffffu, valid);
                if (valid) {
                    const int pos = cnt + __popc(bal & ((1u << lane) - 1u));
                    if (pos < PS) slot[pos] = n0 + (k << 5) + lane;
                }
                cnt += __popc(bal);
            }
        }
        __syncwarp();
        const int c = cnt < PS ? cnt : PS;        // >=1 (self point, dist 0)
        const int first = slot[0];
        const int v = (lane < c) ? slot[lane] : first;
        g_idx[(size_t)wid * PS + lane] = v;
    }
}

// ---------------------------------------------------------------------------
// Kernel 2: group v6 — warp per query, 2-pass channel halves, streaming stores
//   __stcs on all output writes: keep featT L2-resident for the gather,
//   let the 140MB write stream pass through evict-first.  (R9, 28.7us)
// ---------------------------------------------------------------------------
__global__ __launch_bounds__(128) void group_kernel(
    const float* __restrict__ new_xyz, float* __restrict__ out)
{
    __shared__ float4 sf4[4][8 * 33];            // 16,896 B
    const int w    = threadIdx.x >> 5;           // warp in block, 0..3
    const int lane = threadIdx.x & 31;
    const int q    = blockIdx.x * 4 + w;         // global query, 0..16383
    const int b    = q >> 11;
    const int m    = q & (PM - 1);

    // lane j holds neighbor index of sample j
    const int n_reg = g_idx[(size_t)q * PS + lane];

    const float4* fb4 = (const float4*)(g_featT + (size_t)b * PN * PC);
    float4* sm4 = sf4[w];

    // ---- xyz channels (once) ----
    const float* qp = new_xyz + (size_t)q * 3;
    const float qx = qp[0], qy = qp[1], qz = qp[2];
    const float4 p = g_xyz4[(size_t)b * PN + n_reg];

    const size_t chStride = (size_t)PM * PS;     // 65536
    const size_t basep = (size_t)b * OUTC * chStride + (size_t)m * PS + lane;

    __stcs(out + basep + 0 * chStride, p.x - qx);
    __stcs(out + basep + 1 * chStride, p.y - qy);
    __stcs(out + basep + 2 * chStride, p.z - qz);

    const int cg  = lane & 7;                    // quad within half
    const int grp = lane >> 3;                   // 0..3: sample subgroup

#pragma unroll
    for (int h = 0; h < 2; ++h) {
        // ---- Phase B: gather half h ----
#pragma unroll
        for (int it = 0; it < 8; ++it) {
            const int j = (it << 2) | grp;       // sample 0..31
            const int n = __shfl_sync(0xffffffffu, n_reg, j);
            const float4 v = fb4[(size_t)n * 16 + (h << 3) + cg];  // LDG.128
            sm4[cg * 33 + j] = v;                                   // STS.128
        }
        __syncwarp();

        // ---- Phase C: store half h (lane = sample) ----
        float* o = out + basep + (size_t)(3 + (h << 5)) * chStride;
#pragma unroll
        for (int c4 = 0; c4 < 8; ++c4) {
            const float4 v = sm4[c4 * 33 + lane];                   // LDS.128
            __stcs(o + 0 * chStride, v.x);
            __stcs(o + 1 * chStride, v.y);
            __stcs(o + 2 * chStride, v.z);
            __stcs(o + 3 * chStride, v.w);
            o += 4 * chStride;
        }
        __syncwarp();
    }
}

// ---------------------------------------------------------------------------
extern "C" void kernel_launch(void* const* d_in, const int* in_sizes, int n_in,
                              void* d_out, int out_size)
{
    const float* xyz   = nullptr;
    const float* nxyz  = nullptr;
    const float* feats = nullptr;
    for (int i = 0; i < n_in; ++i) {
        if      (in_sizes[i] == PB * PN * 3) xyz   = (const float*)d_in[i];
        else if (in_sizes[i] == PB * PM * 3) nxyz  = (const float*)d_in[i];
        else if (in_sizes[i] == PB * PC * PN) feats = (const float*)d_in[i];
    }
    float* out = (float*)d_out;
    (void)out_size;

    pack_kernel<<<(PB * PN + 255) / 256, 256>>>(xyz);
    mid_kernel<<<1024 + 2048, 256>>>(feats, nxyz);        // transpose ∥ ball query
    group_kernel<<<(PB * PM) / 4, 128>>>(nxyz, out);
}

// round 15
// speedup vs baseline: 1.4666x; 1.4666x over previous
#include <cuda_runtime.h>
#include <cstdint>

// Problem constants
#define PB 8
#define PN 8192
#define PM 2048
#define PC 64
#define PS 32
#define OUTC 67              // 3 + 64
#define R2 1.0f

// Scratch (allocation-free rule: __device__ globals)
__device__ int    g_idx[PB * PM * PS];          // 2 MB
__device__ float  g_featT[PB * PN * PC];        // 16 MB, [b][n][c]
__device__ float4 g_xyz4[PB * PN];              // 1 MB, (x,y,z,p2)

// ---------------------------------------------------------------------------
// Kernel 0: pack xyz -> float4 with precomputed p2 (reference rounding)
// ---------------------------------------------------------------------------
__global__ __launch_bounds__(256) void pack_kernel(const float* __restrict__ xyz)
{
    const int i = blockIdx.x * blockDim.x + threadIdx.x;   // 0 .. B*N-1
    if (i >= PB * PN) return;
    const float x = xyz[i * 3 + 0];
    const float y = xyz[i * 3 + 1];
    const float z = xyz[i * 3 + 2];
    const float p2 = __fadd_rn(__fadd_rn(__fmul_rn(x, x), __fmul_rn(y, y)),
                               __fmul_rn(z, z));
    g_xyz4[i] = make_float4(x, y, z, p2);
}

// ---------------------------------------------------------------------------
// Kernel 1: transpose (DRAM-bound) + ball query (latency-bound) fused by
// blockIdx — independent inputs, complementary bottlenecks. (R8 version)
// blocks 0..1023   : transpose tiles (32c x 128n, float4 loads)
// blocks 1024..3071: ball query, 8 warps/block, 1 query/warp, 256 pts/iter
// ---------------------------------------------------------------------------
__global__ __launch_bounds__(256) void mid_kernel(
    const float* __restrict__ f, const float* __restrict__ new_xyz)
{
    __shared__ union {
        float4 tile[32][33];      // 16,896 B (transpose path)
        int    slots[8][PS];      //  1,024 B (query path)
    } sm;

    const int bid  = blockIdx.x;
    const int tx   = threadIdx.x & 31;
    const int ty   = threadIdx.x >> 5;     // 0..7

    if (bid < 1024) {
        // ---- transpose path ----
        const int b   = bid >> 7;                 // /128
        const int rem = bid & 127;
        const int c0  = (rem >> 6) << 5;          // 0 or 32
        const int n0  = (rem & 63) << 7;          // 0..8064 step 128

#pragma unroll
        for (int k = 0; k < 4; ++k) {
            const int c = ty + (k << 3);          // 0..31
            const float4* src =
                (const float4*)(f + ((size_t)b * PC + c0 + c) * PN + n0);
            sm.tile[c][tx] = src[tx];
        }
        __syncthreads();

        const float* tf = (const float*)&sm.tile[tx][0];  // 132 floats (c=tx)
#pragma unroll
        for (int i = 0; i < 16; ++i) {
            const int n = (i << 3) + ty;          // 0..127
            g_featT[((size_t)b * PN + n0 + n) * PC + c0 + tx] = tf[n];
        }
    } else {
        // ---- ball query path ----
        const int wid  = (bid - 1024) * 8 + ty;   // global query 0..16383
        const int lane = tx;
        const int b = wid >> 11;
        const int m = wid & (PM - 1);

        const float* q = new_xyz + ((size_t)b * PM + m) * 3;
        const float qx = q[0], qy = q[1], qz = q[2];
        const float q2 = __fadd_rn(__fadd_rn(__fmul_rn(qx, qx), __fmul_rn(qy, qy)),
                                   __fmul_rn(qz, qz));

        int* slot = sm.slots[ty];
        const float4* base4 = g_xyz4 + (size_t)b * PN;
        int cnt = 0;
        for (int n0 = 0; n0 < PN && cnt < PS; n0 += 256) {
            float4 cs[8];
#pragma unroll
            for (int k = 0; k < 8; ++k)
                cs[k] = base4[n0 + (k << 5) + lane];
#pragma unroll
            for (int k = 0; k < 8; ++k) {
                const float4 p = cs[k];
                const float qd = __fadd_rn(__fadd_rn(__fmul_rn(qx, p.x), __fmul_rn(qy, p.y)),
                                           __fmul_rn(qz, p.z));
                const float d2 = __fadd_rn(__fadd_rn(q2, p.w), -__fmul_rn(2.0f, qd));
                const bool valid = d2 < R2;
                const unsigned bal = __ballot_sync(0xffffffffu, valid);
                if (valid) {
                    const int pos = cnt + __popc(bal & ((1u << lane) - 1u));
                    if (pos < PS) slot[pos] = n0 + (k << 5) + lane;
                }
                cnt += __popc(bal);
            }
        }
        __syncwarp();
        const int c = cnt < PS ? cnt : PS;        // >=1 (self point, dist 0)
        const int first = slot[0];
        const int v = (lane < c) ? slot[lane] : first;
        g_idx[(size_t)wid * PS + lane] = v;
    }
}

// ---------------------------------------------------------------------------
// Kernel 2: group v6 — byte-identical to R9/R12 (measured 28.7/28.4us):
//   warp per query, 2-pass channel halves, __stcs streaming stores,
//   point coords read from raw xyz (L2-resident).
// ---------------------------------------------------------------------------
__global__ __launch_bounds__(128) void group_kernel(
    const float* __restrict__ xyz, const float* __restrict__ new_xyz,
    float* __restrict__ out)
{
    __shared__ float4 sf4[4][8 * 33];            // 16,896 B
    const int w    = threadIdx.x >> 5;           // warp in block, 0..3
    const int lane = threadIdx.x & 31;
    const int q    = blockIdx.x * 4 + w;         // global query, 0..16383
    const int b    = q >> 11;
    const int m    = q & (PM - 1);

    // lane j holds neighbor index of sample j
    const int n_reg = g_idx[(size_t)q * PS + lane];

    const float4* fb4 = (const float4*)(g_featT + (size_t)b * PN * PC);
    float4* sm4 = sf4[w];

    // ---- xyz channels (once) ----
    const float* qp = new_xyz + (size_t)q * 3;
    const float qx = qp[0], qy = qp[1], qz = qp[2];
    const float* pp = xyz + ((size_t)b * PN + n_reg) * 3;   // L2-resident
    const float px = pp[0], py = pp[1], pz = pp[2];

    const size_t chStride = (size_t)PM * PS;     // 65536
    const size_t basep = (size_t)b * OUTC * chStride + (size_t)m * PS + lane;

    __stcs(out + basep + 0 * chStride, px - qx);
    __stcs(out + basep + 1 * chStride, py - qy);
    __stcs(out + basep + 2 * chStride, pz - qz);

    const int cg  = lane & 7;                    // quad within half
    const int grp = lane >> 3;                   // 0..3: sample subgroup

#pragma unroll
    for (int h = 0; h < 2; ++h) {
        // ---- Phase B: gather half h ----
#pragma unroll
        for (int it = 0; it < 8; ++it) {
            const int j = (it << 2) | grp;       // sample 0..31
            const int n = __shfl_sync(0xffffffffu, n_reg, j);
            const float4 v = fb4[(size_t)n * 16 + (h << 3) + cg];  // LDG.128
            sm4[cg * 33 + j] = v;                                   // STS.128
        }
        __syncwarp();

        // ---- Phase C: store half h (lane = sample) ----
        float* o = out + basep + (size_t)(3 + (h << 5)) * chStride;
#pragma unroll
        for (int c4 = 0; c4 < 8; ++c4) {
            const float4 v = sm4[c4 * 33 + lane];                   // LDS.128
            __stcs(o + 0 * chStride, v.x);
            __stcs(o + 1 * chStride, v.y);
            __stcs(o + 2 * chStride, v.z);
            __stcs(o + 3 * chStride, v.w);
            o += 4 * chStride;
        }
        __syncwarp();
    }
}

// ---------------------------------------------------------------------------
extern "C" void kernel_launch(void* const* d_in, const int* in_sizes, int n_in,
                              void* d_out, int out_size)
{
    const float* xyz   = nullptr;
    const float* nxyz  = nullptr;
    const float* feats = nullptr;
    for (int i = 0; i < n_in; ++i) {
        if      (in_sizes[i] == PB * PN * 3) xyz   = (const float*)d_in[i];
        else if (in_sizes[i] == PB * PM * 3) nxyz  = (const float*)d_in[i];
        else if (in_sizes[i] == PB * PC * PN) feats = (const float*)d_in[i];
    }
    float* out = (float*)d_out;
    (void)out_size;

    pack_kernel<<<(PB * PN + 255) / 256, 256>>>(xyz);
    mid_kernel<<<1024 + 2048, 256>>>(feats, nxyz);        // transpose ∥ ball query
    group_kernel<<<(PB * PM) / 4, 128>>>(xyz, nxyz, out);
}

// round 17
// speedup vs baseline: 1.5883x; 1.0830x over previous
#include <cuda_runtime.h>
#include <cstdint>

// Problem constants
#define PB 8
#define PN 8192
#define PM 2048
#define PC 64
#define PS 32
#define OUTC 67              // 3 + 64
#define R2 1.0f

// Scratch (allocation-free rule: __device__ globals)
__device__ float  g_featT[PB * PN * PC];        // 16 MB, [b][n][c]
__device__ float4 g_xyz4[PB * PN];              // 1 MB, (x,y,z,p2)

// ---------------------------------------------------------------------------
// Kernel A: fused pack (xyz->float4+p2) + transpose (B,C,N)->(B,N,C)
// blocks 0..1023: transpose tiles (32c x 128n, float4 loads)
// blocks 1024..1279: pack
// ---------------------------------------------------------------------------
__global__ __launch_bounds__(256) void pre_kernel(
    const float* __restrict__ xyz, const float* __restrict__ f)
{
    const int bid = blockIdx.x;
    const int tx = threadIdx.x & 31;
    const int ty = threadIdx.x >> 5;      // 0..7

    if (bid < 1024) {
        __shared__ float4 tile[32][33];
        const int b   = bid >> 7;                 // /128
        const int rem = bid & 127;
        const int c0  = (rem >> 6) << 5;          // 0 or 32
        const int n0  = (rem & 63) << 7;          // 0..8064 step 128

#pragma unroll
        for (int k = 0; k < 4; ++k) {
            const int c = ty + (k << 3);          // 0..31
            const float4* src =
                (const float4*)(f + ((size_t)b * PC + c0 + c) * PN + n0);
            tile[c][tx] = src[tx];
        }
        __syncthreads();

        const float* tf = (const float*)&tile[tx][0];     // 132 floats (c=tx)
#pragma unroll
        for (int i = 0; i < 16; ++i) {
            const int n = (i << 3) + ty;          // 0..127
            g_featT[((size_t)b * PN + n0 + n) * PC + c0 + tx] = tf[n];
        }
    } else {
        const int i = (bid - 1024) * 256 + threadIdx.x;   // 0 .. B*N-1
        const float x = xyz[i * 3 + 0];
        const float y = xyz[i * 3 + 1];
        const float z = xyz[i * 3 + 2];
        const float p2 = __fadd_rn(__fadd_rn(__fmul_rn(x, x), __fmul_rn(y, y)),
                                   __fmul_rn(z, z));
        g_xyz4[i] = make_float4(x, y, z, p2);
    }
}

// ---------------------------------------------------------------------------
// Kernel B: FUSED ball query + group — one warp per query, lean footprint
//   bq: 128 pts/iter, 4 INDEPENDENT ballots then ordered bookkeeping
//   group: v6 (2-pass channel halves, __stcs streaming stores)
//   smem 17.4 KB/block, regs reused across phases -> >=8 blocks/SM
// ---------------------------------------------------------------------------
__global__ __launch_bounds__(128) void qg_kernel(
    const float* __restrict__ new_xyz, float* __restrict__ out)
{
    __shared__ float4 sf4[4][8 * 33];            // 16,896 B
    __shared__ int    slots[4][PS];              //     512 B

    const int w    = threadIdx.x >> 5;           // warp in block, 0..3
    const int lane = threadIdx.x & 31;
    const int q    = blockIdx.x * 4 + w;         // global query, 0..16383
    const int b    = q >> 11;
    const int m    = q & (PM - 1);

    // ---- Phase A: ball query ----
    const float* qp = new_xyz + (size_t)q * 3;
    const float qx = qp[0], qy = qp[1], qz = qp[2];
    const float q2 = __fadd_rn(__fadd_rn(__fmul_rn(qx, qx), __fmul_rn(qy, qy)),
                               __fmul_rn(qz, qz));

    int* slot = slots[w];
    const float4* base4 = g_xyz4 + (size_t)b * PN;
    const unsigned ltmask = (1u << lane) - 1u;
    int cnt = 0;
    for (int n0 = 0; n0 < PN && cnt < PS; n0 += 128) {
        float4 cs[4];
#pragma unroll
        for (int k = 0; k < 4; ++k)
            cs[k] = base4[n0 + (k << 5) + lane];

        bool     val[4];
        unsigned bal[4];
#pragma unroll
        for (int k = 0; k < 4; ++k) {            // independent ballots
            const float4 p = cs[k];
            const float qd = __fadd_rn(__fadd_rn(__fmul_rn(qx, p.x), __fmul_rn(qy, p.y)),
                                       __fmul_rn(qz, p.z));
            const float d2 = __fadd_rn(__fadd_rn(q2, p.w), -__fmul_rn(2.0f, qd));
            val[k] = d2 < R2;
            bal[k] = __ballot_sync(0xffffffffu, val[k]);
        }
#pragma unroll
        for (int k = 0; k < 4; ++k) {            // ordered bookkeeping (ALU only)
            if (val[k]) {
                const int pos = cnt + __popc(bal[k] & ltmask);
                if (pos < PS) slot[pos] = n0 + (k << 5) + lane;
            }
            cnt += __popc(bal[k]);
        }
    }
    __syncwarp();
    const int c = cnt < PS ? cnt : PS;           // >=1 (self point, dist 0)
    const int n_reg = (lane < c) ? slot[lane] : slot[0];
    __syncwarp();

    // ---- xyz channels ----
    const float4 p = base4[n_reg];

    const size_t chStride = (size_t)PM * PS;     // 65536
    const size_t basep = (size_t)b * OUTC * chStride + (size_t)m * PS + lane;

    __stcs(out + basep + 0 * chStride, p.x - qx);
    __stcs(out + basep + 1 * chStride, p.y - qy);
    __stcs(out + basep + 2 * chStride, p.z - qz);

    // ---- group: 2-pass channel halves ----
    const float4* fb4 = (const float4*)(g_featT + (size_t)b * PN * PC);
    float4* sm4 = sf4[w];
    const int cg  = lane & 7;                    // quad within half
    const int grp = lane >> 3;                   // 0..3: sample subgroup

#pragma unroll
    for (int h = 0; h < 2; ++h) {
        // Phase B: gather half h
#pragma unroll
        for (int it = 0; it < 8; ++it) {
            const int j = (it << 2) | grp;       // sample 0..31
            const int n = __shfl_sync(0xffffffffu, n_reg, j);
            const float4 v = fb4[(size_t)n * 16 + (h << 3) + cg];  // LDG.128
            sm4[cg * 33 + j] = v;                                   // STS.128
        }
        __syncwarp();

        // Phase C: store half h (lane = sample)
        float* o = out + basep + (size_t)(3 + (h << 5)) * chStride;
#pragma unroll
        for (int c4 = 0; c4 < 8; ++c4) {
            const float4 v = sm4[c4 * 33 + lane];                   // LDS.128
            __stcs(o + 0 * chStride, v.x);
            __stcs(o + 1 * chStride, v.y);
            __stcs(o + 2 * chStride, v.z);
            __stcs(o + 3 * chStride, v.w);
            o += 4 * chStride;
        }
        __syncwarp();
    }
}

// ---------------------------------------------------------------------------
extern "C" void kernel_launch(void* const* d_in, const int* in_sizes, int n_in,
                              void* d_out, int out_size)
{
    const float* xyz   = nullptr;
    const float* nxyz  = nullptr;
    const float* feats = nullptr;
    for (int i = 0; i < n_in; ++i) {
        if      (in_sizes[i] == PB * PN * 3) xyz   = (const float*)d_in[i];
        else if (in_sizes[i] == PB * PM * 3) nxyz  = (const float*)d_in[i];
        else if (in_sizes[i] == PB * PC * PN) feats = (const float*)d_in[i];
    }
    float* out = (float*)d_out;
    (void)out_size;

    pre_kernel<<<1024 + 256, 256>>>(xyz, feats);          // pack + transpose
    qg_kernel<<<(PB * PM) / 4, 128>>>(nxyz, out);         // fused query+group
}